// round 10
// baseline (speedup 1.0000x reference)
#include <cuda_runtime.h>
#include <cuda_bf16.h>

#define IMG_W 1024
#define IMG_H 1024
#define NC_TOTAL 48
#define ROWS 16
#define NTOT (ROWS + 2)    // 18 input rows
#define NA 9               // batch A: rows y0-1 .. y0+7
#define NB 9               // batch B: rows y0+8 .. y0+16

// v8 = v7 scaled to 16-row tiles with two 9-row load batches.
// Batch B is issued at iteration r=7 so peak live buffer stays 10 float4
// (vA[7],vA[8] + vB[0..8]) == v7's register footprint, while per-warp load
// duty cycle doubles and read amplification drops to 1.125x.
__global__ void __launch_bounds__(256, 3) normconv3x3_v8(
    const float* __restrict__ x,
    const float* __restrict__ wt,
    float* __restrict__ out)
{
    const int lane = threadIdx.x & 31;
    const int x0 = (int)threadIdx.x << 2;          // 0..1020
    const int b = blockIdx.x;
    const int y0 = (b & 63) << 4;                  // 64 16-row tiles
    const int nc = b >> 6;                         // 0..47
    const int c = nc % 3;

    const float* base = x + ((size_t)nc << 20) + x0;
    const bool interior = (y0 != 0) && (y0 != IMG_H - ROWS);

    // ---- Batch A: 9 front-batched row loads (rows y0-1 .. y0+7) ----
    float4 vA[NA];
    if (interior) {
#pragma unroll
        for (int i = 0; i < NA; i++)
            vA[i] = *reinterpret_cast<const float4*>(base + (size_t)(y0 - 1 + i) * IMG_W);
    } else {
#pragma unroll
        for (int i = 0; i < NA; i++) {
            const int rr = y0 - 1 + i;
            const int rc = min(IMG_H - 1, max(0, rr));
            vA[i] = *reinterpret_cast<const float4*>(base + (size_t)rc * IMG_W);
            if (rr != rc) vA[i] = make_float4(0.f, 0.f, 0.f, 0.f);
        }
    }

    // Weights after the bulk loads are in flight
    float w[9];
    float ws2 = 0.f;
#pragma unroll
    for (int k = 0; k < 9; k++) { w[k] = __ldg(&wt[c * 9 + k]); ws2 += w[k] * w[k]; }
    const float winv = rsqrtf(ws2);
#pragma unroll
    for (int k = 0; k < 9; k++) w[k] *= winv;

    float4 vB[NB];
    float num[ROWS][4], sq[ROWS][4];
    float* op = out + ((size_t)nc << 20) + (size_t)y0 * IMG_W + x0;

    // Prologue halo for input row 0 (global row y0-1)
    float h0c = __shfl_up_sync(0xffffffffu, vA[0].w, 1);
    float h5c = __shfl_down_sync(0xffffffffu, vA[0].x, 1);
    {
        const int rr = y0 - 1;
        if (lane == 0)  h0c = (x0 > 0 && rr >= 0)          ? __ldg(base + (size_t)rr * IMG_W - 1) : 0.f;
        if (lane == 31) h5c = (x0 + 4 < IMG_W && rr >= 0)  ? __ldg(base + (size_t)rr * IMG_W + 4) : 0.f;
    }

#pragma unroll
    for (int r = 0; r < NTOT; r++) {
        // Issue batch B loads once vA[0..6] are dead (live: vA[7],vA[8] + vB)
        if (r == 7) {
            if (interior) {
#pragma unroll
                for (int i = 0; i < NB; i++)
                    vB[i] = *reinterpret_cast<const float4*>(base + (size_t)(y0 + 8 + i) * IMG_W);
            } else {
#pragma unroll
                for (int i = 0; i < NB; i++) {
                    const int rr = y0 + 8 + i;
                    const int rc = min(IMG_H - 1, max(0, rr));
                    vB[i] = *reinterpret_cast<const float4*>(base + (size_t)rc * IMG_W);
                    if (rr != rc) vB[i] = make_float4(0.f, 0.f, 0.f, 0.f);
                }
            }
        }

        const float4 vc = (r < NA) ? vA[r] : vB[r - NA];

        // Pipeline: next row's halo before this row's compute
        float h0n = 0.f, h5n = 0.f;
        if (r + 1 < NTOT) {
            const float4 vn = (r + 1 < NA) ? vA[r + 1] : vB[r + 1 - NA];
            h0n = __shfl_up_sync(0xffffffffu, vn.w, 1);
            h5n = __shfl_down_sync(0xffffffffu, vn.x, 1);
            const int rr = y0 + r;                 // global row of vn
            if (lane == 0)  h0n = (x0 > 0 && rr < IMG_H)         ? __ldg(base + (size_t)rr * IMG_W - 1) : 0.f;
            if (lane == 31) h5n = (x0 + 4 < IMG_W && rr < IMG_H) ? __ldg(base + (size_t)rr * IMG_W + 4) : 0.f;
        }

        const float a[6] = { h0c, vc.x, vc.y, vc.z, vc.w, h5c };

        float p[6];
#pragma unroll
        for (int i = 0; i < 6; i++) p[i] = a[i] * a[i];
        const float u = p[1] + p[2];
        const float t = p[3] + p[4];
        const float s[4] = { p[0] + u, u + p[3], p[2] + t, t + p[5] };

#pragma unroll
        for (int o = 0; o < ROWS; o++) {
            const int k = r - o;                    // weight row for this (input,output) pair
            if (k == 0) {
#pragma unroll
                for (int j = 0; j < 4; j++) {
                    num[o][j] = fmaf(w[0], a[j], fmaf(w[1], a[j + 1], w[2] * a[j + 2]));
                    sq[o][j] = s[j];
                }
            } else if (k == 1 || k == 2) {
                const float w0 = w[k * 3 + 0], w1 = w[k * 3 + 1], w2 = w[k * 3 + 2];
#pragma unroll
                for (int j = 0; j < 4; j++) {
                    num[o][j] = fmaf(w0, a[j], fmaf(w1, a[j + 1], fmaf(w2, a[j + 2], num[o][j])));
                    sq[o][j] += s[j];
                }
            }
        }

        // output row (r-2) complete after consuming input row r
        if (r >= 2) {
            const int o = r - 2;
            float4 ov;
            ov.x = num[o][0] * rsqrtf(sq[o][0]);
            ov.y = num[o][1] * rsqrtf(sq[o][1]);
            ov.z = num[o][2] * rsqrtf(sq[o][2]);
            ov.w = num[o][3] * rsqrtf(sq[o][3]);
            *reinterpret_cast<float4*>(op + (size_t)o * IMG_W) = ov;
        }

        h0c = h0n; h5c = h5n;
    }
}

extern "C" void kernel_launch(void* const* d_in, const int* in_sizes, int n_in,
                              void* d_out, int out_size) {
    const float* x  = (const float*)d_in[0];
    const float* wt = (const float*)d_in[1];
    float* out = (float*)d_out;

    dim3 grid(NC_TOTAL * (IMG_H / ROWS));   // 3072 blocks, 256 threads = full row width
    normconv3x3_v8<<<grid, 256>>>(x, wt, out);
}